// round 7
// baseline (speedup 1.0000x reference)
#include <cuda_runtime.h>
#include <cuda_bf16.h>
#include <cstddef>

// ---------------------------------------------------------------------------
// Model_53901839564895: CNN forward (packed f32x2 FMA edition)
//   x [512,3,128,128]
//   conv1 5x5 pad1 (3->5) -> relu -> BN(eval) -> maxpool 3,2,1   -> [512,5,63,63]
//   conv2 3x3 pad1 (5->9) -> relu -> maxpool 3,2,1               -> [512,9,32,32]
//   conv3 3x3 pad1 (9->16) -> flatten -> FC(16384->6) -> softmax
// Weight layout quirk: effective weight = raw buffer indexed as
//   w[((c*KH+ki)*KW+kj)*COUT + o]
// ---------------------------------------------------------------------------

#define BATCH 512

typedef unsigned long long u64;

__device__ __forceinline__ u64 pack2(float lo, float hi) {
    u64 d; asm("mov.b64 %0, {%1, %2};" : "=l"(d) : "f"(lo), "f"(hi)); return d;
}
__device__ __forceinline__ void unpack2(u64 v, float& lo, float& hi) {
    asm("mov.b64 {%0, %1}, %2;" : "=f"(lo), "=f"(hi) : "l"(v));
}
// packed fp32x2 FMA (sm_103a; ptxas never emits this from C++)
__device__ __forceinline__ u64 fma2(u64 a, u64 b, u64 c) {
    u64 d; asm("fma.rn.f32x2 %0, %1, %2, %3;" : "=l"(d) : "l"(a), "l"(b), "l"(c));
    return d;
}

// Static scratch: p1 [512,5,63,63], p2 [512,9,32,32]
__device__ float g_p1[(size_t)BATCH * 5 * 63 * 63];
__device__ float g_p2[(size_t)BATCH * 9 * 32 * 32];

// ===========================================================================
// K1: conv1(5x5,pad1)+relu+BN+maxpool(3,2,1).
// Pooled tile 16x8 -> conv tile 33x17. x-groups of 4 -> 153 items,
// 160 threads, one item/thread. Accumulators packed f32x2 (xi 0,1 | 2,3).
// Weights duplicated (w,w) in smem -> broadcast LDS.64 feeds FMA2 directly.
// grid (4,8,512).
// ===========================================================================
__global__ __launch_bounds__(160, 6) void k1_conv_bn_pool(
    const float* __restrict__ x, const float* __restrict__ k1,
    const float* __restrict__ gamma, const float* __restrict__ beta)
{
    __shared__ u64 sw2[375];                      // 5x5x3x5, duplicated lanes
    __shared__ float sscale[5], sbeta[5];
    __shared__ __align__(16) float sinf[63 * 40]; // 3ch x 21 rows, width 40 (37 used)
    __shared__ float sconv[5][17][33];

    const int tid = threadIdx.x;
    const int b   = blockIdx.z;
    const int px0 = blockIdx.x * 16;
    const int py0 = blockIdx.y * 8;
    const int cy0 = 2 * py0 - 1;
    const int cx0 = 2 * px0 - 1;

    for (int i = tid; i < 375; i += 160) { float w = k1[i]; sw2[i] = pack2(w, w); }
    if (tid < 5) {
        sscale[tid] = gamma[tid] * rsqrtf(1.0f + 1e-5f);
        sbeta[tid]  = beta[tid];
    }

    // Halo load, row-strided. Cols 37..39 zero-filled for safe float4 reads.
    const float* xb = x + (size_t)b * 3 * 128 * 128;
    {
        const int tj = tid % 40;
        const int r0 = tid / 40;                  // 0..3
        const int ix = cx0 - 1 + tj;
        #pragma unroll 1
        for (int row = r0; row < 63; row += 4) {
            int c  = row / 21;
            int li = row - c * 21;
            int iy = cy0 - 1 + li;
            float v = 0.0f;
            if (tj < 37 && iy >= 0 && iy < 128 && ix >= 0 && ix < 128)
                v = xb[(c * 128 + iy) * 128 + ix];
            sinf[row * 40 + tj] = v;
        }
    }
    __syncthreads();

    if (tid < 153) {
        const int y  = tid / 9;
        const int x0 = (tid % 9) * 4;             // 0,4,...,32

        u64 acc01[5], acc23[5];
        #pragma unroll
        for (int o = 0; o < 5; o++) { acc01[o] = 0ull; acc23[o] = 0ull; }

        #pragma unroll
        for (int c = 0; c < 3; c++) {
            #pragma unroll
            for (int ki = 0; ki < 5; ki++) {
                const float4* rp =
                    reinterpret_cast<const float4*>(&sinf[(c * 21 + y + ki) * 40 + x0]);
                float4 a = rp[0], bq = rp[1];
                float r[8] = {a.x, a.y, a.z, a.w, bq.x, bq.y, bq.z, bq.w};
                u64 p[7];
                #pragma unroll
                for (int k = 0; k < 7; k++) p[k] = pack2(r[k], r[k + 1]);
                #pragma unroll
                for (int kj = 0; kj < 5; kj++) {
                    #pragma unroll
                    for (int o = 0; o < 5; o++) {
                        u64 w = sw2[((c * 5 + ki) * 5 + kj) * 5 + o];
                        acc01[o] = fma2(p[kj],     w, acc01[o]);
                        acc23[o] = fma2(p[kj + 2], w, acc23[o]);
                    }
                }
            }
        }
        const int cy = cy0 + y;
        const bool yok = (cy >= 0 && cy < 126);
        #pragma unroll
        for (int o = 0; o < 5; o++) {
            float v0, v1, v2, v3;
            unpack2(acc01[o], v0, v1);
            unpack2(acc23[o], v2, v3);
            float vv[4] = {v0, v1, v2, v3};
            #pragma unroll
            for (int xi = 0; xi < 4; xi++) {
                int tx = x0 + xi;
                if (tx < 33) {
                    int cx = cx0 + tx;
                    bool ok = yok && (cx >= 0) && (cx < 126);
                    float v = 0.0f;               // zero pool-pad matches reference
                    if (ok) v = fmaf(fmaxf(vv[xi], 0.0f), sscale[o], sbeta[o]);
                    sconv[o][y][tx] = v;
                }
            }
        }
    }
    __syncthreads();

    float* p1b = g_p1 + (size_t)b * 5 * 63 * 63;
    for (int idx = tid; idx < 5 * 128; idx += 160) {
        int o = idx >> 7, rem = idx & 127;
        int ly = rem >> 4, lx = rem & 15;
        int py = py0 + ly, px = px0 + lx;
        if (py < 63 && px < 63) {
            float m = -1e30f;
            #pragma unroll
            for (int dy = 0; dy < 3; dy++)
                #pragma unroll
                for (int dx = 0; dx < 3; dx++)
                    m = fmaxf(m, sconv[o][2 * ly + dy][2 * lx + dx]);
            p1b[(o * 63 + py) * 63 + px] = m;
        }
    }
}

// ===========================================================================
// K2: conv2(3x3,pad1, 5->9)+relu+maxpool(3,2,1): 63x63 -> 32x32.
// Same structure, packed accumulators. grid (2,4,512).
// ===========================================================================
__global__ __launch_bounds__(160, 5) void k2_conv_pool(const float* __restrict__ k2)
{
    __shared__ u64 sw2[405];                      // 3x3x5x9 duplicated
    __shared__ __align__(16) float sinf[95 * 40]; // 5ch x 19 rows, width 40 (35 used)
    __shared__ float sconv[9][17][33];

    const int tid = threadIdx.x;
    const int b   = blockIdx.z;
    const int px0 = blockIdx.x * 16;
    const int py0 = blockIdx.y * 8;
    const int cy0 = 2 * py0 - 1;
    const int cx0 = 2 * px0 - 1;

    for (int i = tid; i < 405; i += 160) { float w = k2[i]; sw2[i] = pack2(w, w); }

    const float* pin = g_p1 + (size_t)b * 5 * 63 * 63;
    {
        const int tj = tid % 40;
        const int r0 = tid / 40;
        const int ix = cx0 - 1 + tj;
        #pragma unroll 1
        for (int row = r0; row < 95; row += 4) {
            int c  = row / 19;
            int li = row - c * 19;
            int iy = cy0 - 1 + li;
            float v = 0.0f;
            if (tj < 35 && iy >= 0 && iy < 63 && ix >= 0 && ix < 63)
                v = pin[(c * 63 + iy) * 63 + ix];
            sinf[row * 40 + tj] = v;
        }
    }
    __syncthreads();

    if (tid < 153) {
        const int y  = tid / 9;
        const int x0 = (tid % 9) * 4;

        u64 acc01[9], acc23[9];
        #pragma unroll
        for (int o = 0; o < 9; o++) { acc01[o] = 0ull; acc23[o] = 0ull; }

        #pragma unroll
        for (int c = 0; c < 5; c++) {
            #pragma unroll
            for (int ki = 0; ki < 3; ki++) {
                const float4* rp =
                    reinterpret_cast<const float4*>(&sinf[(c * 19 + y + ki) * 40 + x0]);
                float4 a = rp[0], bq = rp[1];
                float r[8] = {a.x, a.y, a.z, a.w, bq.x, bq.y, bq.z, bq.w};
                u64 p[5];
                #pragma unroll
                for (int k = 0; k < 5; k++) p[k] = pack2(r[k], r[k + 1]);
                #pragma unroll
                for (int kj = 0; kj < 3; kj++) {
                    #pragma unroll
                    for (int o = 0; o < 9; o++) {
                        u64 w = sw2[((c * 3 + ki) * 3 + kj) * 9 + o];
                        acc01[o] = fma2(p[kj],     w, acc01[o]);
                        acc23[o] = fma2(p[kj + 2], w, acc23[o]);
                    }
                }
            }
        }
        const int cy = cy0 + y;
        const bool yok = (cy >= 0 && cy < 63);
        #pragma unroll
        for (int o = 0; o < 9; o++) {
            float v0, v1, v2, v3;
            unpack2(acc01[o], v0, v1);
            unpack2(acc23[o], v2, v3);
            float vv[4] = {v0, v1, v2, v3};
            #pragma unroll
            for (int xi = 0; xi < 4; xi++) {
                int tx = x0 + xi;
                if (tx < 33) {
                    int cx = cx0 + tx;
                    bool ok = yok && (cx >= 0) && (cx < 63);
                    float v = 0.0f;
                    if (ok) v = fmaxf(vv[xi], 0.0f);
                    sconv[o][y][tx] = v;
                }
            }
        }
    }
    __syncthreads();

    float* p2b = g_p2 + (size_t)b * 9 * 32 * 32;
    for (int idx = tid; idx < 9 * 128; idx += 160) {
        int o = idx >> 7, rem = idx & 127;
        int ly = rem >> 4, lx = rem & 15;
        int py = py0 + ly, px = px0 + lx;
        float m = -1e30f;
        #pragma unroll
        for (int dy = 0; dy < 3; dy++)
            #pragma unroll
            for (int dx = 0; dx < 3; dx++)
                m = fmaxf(m, sconv[o][2 * ly + dy][2 * lx + dx]);
        p2b[(o * 32 + py) * 32 + px] = m;
    }
}

// ===========================================================================
// K3: conv3(3x3,pad1, 9->16) + FC(16384->6) + softmax. One block per image.
// Thread t owns 4 x positions at row y=t/8, all 16 couts; conv accumulators
// and FC both packed f32x2. grid (512), block 256.
// ===========================================================================
__global__ __launch_bounds__(256) void k3_conv_fc_softmax(
    const float* __restrict__ k3, const float* __restrict__ fc_w,
    const float* __restrict__ fc_b, float* __restrict__ out)
{
    __shared__ float sin[9 * 32 * 32];   // 9216
    __shared__ u64 sw2[1296];            // 3x3x9x16 duplicated
    __shared__ float sred[8 * 6];
    __shared__ float slog[6];

    const int tid = threadIdx.x;
    const int b   = blockIdx.x;

    const float* pin = g_p2 + (size_t)b * 9 * 1024;
    for (int idx = tid; idx < 9216; idx += 256) sin[idx] = pin[idx];
    for (int idx = tid; idx < 1296; idx += 256) { float w = k3[idx]; sw2[idx] = pack2(w, w); }
    __syncthreads();

    const int y  = tid >> 3;
    const int x0 = (tid & 7) * 4;

    u64 cacc01[16], cacc23[16];
    #pragma unroll
    for (int o = 0; o < 16; o++) { cacc01[o] = 0ull; cacc23[o] = 0ull; }

    for (int c = 0; c < 9; c++) {
        #pragma unroll
        for (int ki = 0; ki < 3; ki++) {
            int iy = y + ki - 1;
            float r[6];
            #pragma unroll
            for (int j = 0; j < 6; j++) {
                int ix = x0 - 1 + j;
                r[j] = (iy >= 0 && iy < 32 && ix >= 0 && ix < 32)
                           ? sin[(c * 32 + iy) * 32 + ix] : 0.0f;
            }
            u64 p[5];
            #pragma unroll
            for (int k = 0; k < 5; k++) p[k] = pack2(r[k], r[k + 1]);
            #pragma unroll
            for (int kj = 0; kj < 3; kj++) {
                #pragma unroll
                for (int o = 0; o < 16; o++) {
                    u64 w = sw2[((c * 3 + ki) * 3 + kj) * 16 + o];
                    cacc01[o] = fma2(p[kj],     w, cacc01[o]);
                    cacc23[o] = fma2(p[kj + 2], w, cacc23[o]);
                }
            }
        }
    }

    // FC: flat f = o*1024 + y*32 + x0 + xi. fc_w row loaded as ulonglong2
    // (two packed f32x2 lanes); horizontal add at the end.
    const int base = y * 32 + x0;
    float facc[6];
    #pragma unroll
    for (int j = 0; j < 6; j++) {
        const float* wj = fc_w + (size_t)j * 16384 + base;
        u64 f2 = 0ull;
        #pragma unroll
        for (int o = 0; o < 16; o++) {
            ulonglong2 wv = *reinterpret_cast<const ulonglong2*>(wj + o * 1024);
            f2 = fma2(cacc01[o], wv.x, f2);
            f2 = fma2(cacc23[o], wv.y, f2);
        }
        float lo, hi; unpack2(f2, lo, hi);
        facc[j] = lo + hi;
    }

    #pragma unroll
    for (int j = 0; j < 6; j++) {
        float v = facc[j];
        #pragma unroll
        for (int off = 16; off > 0; off >>= 1)
            v += __shfl_down_sync(0xffffffffu, v, off);
        if ((tid & 31) == 0) sred[(tid >> 5) * 6 + j] = v;
    }
    __syncthreads();
    if (tid < 6) {
        float s = fc_b[tid];
        #pragma unroll
        for (int w = 0; w < 8; w++) s += sred[w * 6 + tid];
        slog[tid] = s;
    }
    __syncthreads();
    if (tid == 0) {
        float mx = slog[0];
        #pragma unroll
        for (int j = 1; j < 6; j++) mx = fmaxf(mx, slog[j]);
        float e[6], s = 0.0f;
        #pragma unroll
        for (int j = 0; j < 6; j++) { e[j] = expf(slog[j] - mx); s += e[j]; }
        float inv = 1.0f / s;
        #pragma unroll
        for (int j = 0; j < 6; j++) out[b * 6 + j] = e[j] * inv;
    }
}

// ===========================================================================
extern "C" void kernel_launch(void* const* d_in, const int* in_sizes, int n_in,
                              void* d_out, int out_size)
{
    const float* x     = (const float*)d_in[0];
    const float* k1    = (const float*)d_in[1];
    const float* gamma = (const float*)d_in[2];
    const float* beta  = (const float*)d_in[3];
    const float* k2    = (const float*)d_in[4];
    const float* k3    = (const float*)d_in[5];
    const float* fc_w  = (const float*)d_in[6];
    const float* fc_b  = (const float*)d_in[7];
    float* out = (float*)d_out;

    k1_conv_bn_pool<<<dim3(4, 8, BATCH), 160>>>(x, k1, gamma, beta);
    k2_conv_pool<<<dim3(2, 4, BATCH), 160>>>(k2);
    k3_conv_fc_softmax<<<BATCH, 256>>>(k3, fc_w, fc_b, out);
}

// round 8
// speedup vs baseline: 1.2784x; 1.2784x over previous
#include <cuda_runtime.h>
#include <cuda_bf16.h>
#include <cstddef>

// ---------------------------------------------------------------------------
// Model_53901839564895: CNN forward
//   x [512,3,128,128]
//   conv1 5x5 pad1 (3->5) -> relu -> BN(eval) -> maxpool 3,2,1   -> [512,5,63,63]
//   conv2 3x3 pad1 (5->9) -> relu -> maxpool 3,2,1               -> [512,9,32,32]
//   conv3 3x3 pad1 (9->16) -> flatten -> FC(16384->6) -> softmax
// Weight layout quirk: effective weight = raw buffer indexed as
//   w[((c*KH+ki)*KW+kj)*COUT + o]
// R8 = R5 structure (best known: K1@258us) + occupancy bump (48-reg K1 -> 7 CTAs/SM)
// ---------------------------------------------------------------------------

#define BATCH 512

// Static scratch: p1 [512,5,63,63], p2 [512,9,32,32]
__device__ float g_p1[(size_t)BATCH * 5 * 63 * 63];
__device__ float g_p2[(size_t)BATCH * 9 * 32 * 32];

// ===========================================================================
// K1: conv1(5x5,pad1)+relu+BN+maxpool(3,2,1).
// Pooled tile 16x8 per block -> conv tile 33x17 -> 187 work items.
// 192 threads, ONE conv item per thread. launch_bounds(192,7) caps regs at 48
// -> 7 CTAs/SM (R5 had 56 regs -> 6 CTAs, occ 53.8%). grid (4,8,512).
// ===========================================================================
__global__ __launch_bounds__(192, 7) void k1_conv_bn_pool(
    const float* __restrict__ x, const float* __restrict__ k1,
    const float* __restrict__ gamma, const float* __restrict__ beta)
{
    __shared__ float sw[375];            // 5x5x3x5
    __shared__ float sscale[5], sbeta[5];
    __shared__ float sin[3][21][37];     // input halo: 17 conv rows + 4
    __shared__ float sconv[5][17][33];   // post-BN conv tile (0 where pad)

    const int tid = threadIdx.x;
    const int b   = blockIdx.z;
    const int px0 = blockIdx.x * 16;
    const int py0 = blockIdx.y * 8;
    const int cy0 = 2 * py0 - 1;         // conv-row origin (pool pad 1)
    const int cx0 = 2 * px0 - 1;

    for (int i = tid; i < 375; i += 192) sw[i] = k1[i];
    if (tid < 5) {
        sscale[tid] = gamma[tid] * rsqrtf(1.0f + 1e-5f);
        sbeta[tid]  = beta[tid];
    }

    // Input halo rows cy0-1 .. cy0+19 (conv pad 1, kernel 5)
    const float* xb = x + (size_t)b * 3 * 128 * 128;
    for (int idx = tid; idx < 3 * 21 * 37; idx += 192) {
        int c = idx / (21 * 37);
        int r = idx % (21 * 37);
        int li = r / 37, lj = r % 37;
        int iy = cy0 - 1 + li, ix = cx0 - 1 + lj;
        float v = 0.0f;
        if (iy >= 0 && iy < 128 && ix >= 0 && ix < 128)
            v = xb[(c * 128 + iy) * 128 + ix];
        sin[c][li][lj] = v;
    }
    __syncthreads();

    // One item per thread: y in [0,17), x-group of 3 in [0,11)
    if (tid < 187) {
        const int y  = tid / 11;
        const int x0 = (tid % 11) * 3;

        float acc[3][5];
        #pragma unroll
        for (int xi = 0; xi < 3; xi++)
            #pragma unroll
            for (int o = 0; o < 5; o++) acc[xi][o] = 0.0f;

        #pragma unroll
        for (int c = 0; c < 3; c++) {
            #pragma unroll
            for (int ki = 0; ki < 5; ki++) {
                float r[7];
                #pragma unroll
                for (int j = 0; j < 7; j++) r[j] = sin[c][y + ki][x0 + j];
                #pragma unroll
                for (int kj = 0; kj < 5; kj++) {
                    const float* wp = &sw[((c * 5 + ki) * 5 + kj) * 5];
                    #pragma unroll
                    for (int o = 0; o < 5; o++) {
                        float wv = wp[o];
                        acc[0][o] = fmaf(r[kj],     wv, acc[0][o]);
                        acc[1][o] = fmaf(r[kj + 1], wv, acc[1][o]);
                        acc[2][o] = fmaf(r[kj + 2], wv, acc[2][o]);
                    }
                }
            }
        }
        const int cy = cy0 + y;
        const bool yok = (cy >= 0 && cy < 126);
        #pragma unroll
        for (int xi = 0; xi < 3; xi++) {
            int cx = cx0 + x0 + xi;
            bool ok = yok && (cx >= 0) && (cx < 126);
            #pragma unroll
            for (int o = 0; o < 5; o++) {
                float v = 0.0f;  // zero pool-pad matches reference
                if (ok) v = fmaf(fmaxf(acc[xi][o], 0.0f), sscale[o], sbeta[o]);
                sconv[o][y][x0 + xi] = v;
            }
        }
    }
    __syncthreads();

    // Maxpool 3x3 stride 2 over the 16x8 pooled tile, 5 channels = 640 outs
    float* p1b = g_p1 + (size_t)b * 5 * 63 * 63;
    for (int idx = tid; idx < 5 * 128; idx += 192) {
        int o = idx >> 7, rem = idx & 127;
        int ly = rem >> 4, lx = rem & 15;
        int py = py0 + ly, px = px0 + lx;
        if (py < 63 && px < 63) {
            float m = -1e30f;
            #pragma unroll
            for (int dy = 0; dy < 3; dy++)
                #pragma unroll
                for (int dx = 0; dx < 3; dx++)
                    m = fmaxf(m, sconv[o][2 * ly + dy][2 * lx + dx]);
            p1b[(o * 63 + py) * 63 + px] = m;
        }
    }
}

// ===========================================================================
// K2: conv2(3x3,pad1, 5->9)+relu+maxpool(3,2,1): 63x63 -> 32x32.
// Pooled tile 16x8 -> conv 33x17 -> 187 items, 192 threads, one item/thread.
// grid (2,4,512). 6 CTAs/SM (27 live accumulators; 48 regs would spill).
// ===========================================================================
__global__ __launch_bounds__(192, 6) void k2_conv_pool(const float* __restrict__ k2)
{
    __shared__ float sw[405];            // 3x3x5x9
    __shared__ float sin[5][19][35];     // 17 conv rows + 2 halo
    __shared__ float sconv[9][17][33];

    const int tid = threadIdx.x;
    const int b   = blockIdx.z;
    const int px0 = blockIdx.x * 16;
    const int py0 = blockIdx.y * 8;
    const int cy0 = 2 * py0 - 1;
    const int cx0 = 2 * px0 - 1;

    for (int i = tid; i < 405; i += 192) sw[i] = k2[i];

    const float* pin = g_p1 + (size_t)b * 5 * 63 * 63;
    for (int idx = tid; idx < 5 * 19 * 35; idx += 192) {
        int c = idx / (19 * 35);
        int r = idx % (19 * 35);
        int li = r / 35, lj = r % 35;
        int iy = cy0 - 1 + li, ix = cx0 - 1 + lj;
        float v = 0.0f;
        if (iy >= 0 && iy < 63 && ix >= 0 && ix < 63)
            v = pin[(c * 63 + iy) * 63 + ix];
        sin[c][li][lj] = v;
    }
    __syncthreads();

    if (tid < 187) {
        const int y  = tid / 11;
        const int x0 = (tid % 11) * 3;

        float acc[3][9];
        #pragma unroll
        for (int xi = 0; xi < 3; xi++)
            #pragma unroll
            for (int o = 0; o < 9; o++) acc[xi][o] = 0.0f;

        #pragma unroll
        for (int c = 0; c < 5; c++) {
            #pragma unroll
            for (int ki = 0; ki < 3; ki++) {
                float r[5];
                #pragma unroll
                for (int j = 0; j < 5; j++) r[j] = sin[c][y + ki][x0 + j];
                #pragma unroll
                for (int kj = 0; kj < 3; kj++) {
                    const float* wp = &sw[((c * 3 + ki) * 3 + kj) * 9];
                    #pragma unroll
                    for (int o = 0; o < 9; o++) {
                        float wv = wp[o];
                        acc[0][o] = fmaf(r[kj],     wv, acc[0][o]);
                        acc[1][o] = fmaf(r[kj + 1], wv, acc[1][o]);
                        acc[2][o] = fmaf(r[kj + 2], wv, acc[2][o]);
                    }
                }
            }
        }
        const int cy = cy0 + y;
        const bool yok = (cy >= 0 && cy < 63);
        #pragma unroll
        for (int xi = 0; xi < 3; xi++) {
            int cx = cx0 + x0 + xi;
            bool ok = yok && (cx >= 0) && (cx < 63);
            #pragma unroll
            for (int o = 0; o < 9; o++) {
                float v = 0.0f;
                if (ok) v = fmaxf(acc[xi][o], 0.0f);
                sconv[o][y][x0 + xi] = v;
            }
        }
    }
    __syncthreads();

    float* p2b = g_p2 + (size_t)b * 9 * 32 * 32;
    for (int idx = tid; idx < 9 * 128; idx += 192) {
        int o = idx >> 7, rem = idx & 127;
        int ly = rem >> 4, lx = rem & 15;
        int py = py0 + ly, px = px0 + lx;   // always < 32
        float m = -1e30f;
        #pragma unroll
        for (int dy = 0; dy < 3; dy++)
            #pragma unroll
            for (int dx = 0; dx < 3; dx++)
                m = fmaxf(m, sconv[o][2 * ly + dy][2 * lx + dx]);
        p2b[(o * 32 + py) * 32 + px] = m;
    }
}

// ===========================================================================
// K3: conv3(3x3,pad1, 9->16) + FC(16384->6) + softmax. One block per image.
// Thread t owns 4 consecutive x positions at row y = t/8, all 16 couts.
// grid (512), block 256, 2 CTAs/SM. Input staged via float4.
// ===========================================================================
__global__ __launch_bounds__(256, 2) void k3_conv_fc_softmax(
    const float* __restrict__ k3, const float* __restrict__ fc_w,
    const float* __restrict__ fc_b, float* __restrict__ out)
{
    __shared__ __align__(16) float sin[9 * 32 * 32];   // 9216
    __shared__ float sw[1296];           // 3x3x9x16
    __shared__ float sred[8 * 6];
    __shared__ float slog[6];

    const int tid = threadIdx.x;
    const int b   = blockIdx.x;

    // Vectorized stage: 9216 floats = 2304 float4
    const float4* pin4 = reinterpret_cast<const float4*>(g_p2 + (size_t)b * 9 * 1024);
    float4* sin4 = reinterpret_cast<float4*>(sin);
    for (int idx = tid; idx < 2304; idx += 256) sin4[idx] = pin4[idx];
    for (int idx = tid; idx < 1296; idx += 256) sw[idx] = k3[idx];
    __syncthreads();

    const int y  = tid >> 3;
    const int x0 = (tid & 7) * 4;

    float cacc[4][16];
    #pragma unroll
    for (int xi = 0; xi < 4; xi++)
        #pragma unroll
        for (int o = 0; o < 16; o++) cacc[xi][o] = 0.0f;

    for (int c = 0; c < 9; c++) {
        #pragma unroll
        for (int ki = 0; ki < 3; ki++) {
            int iy = y + ki - 1;
            float r[6];
            #pragma unroll
            for (int j = 0; j < 6; j++) {
                int ix = x0 - 1 + j;
                r[j] = (iy >= 0 && iy < 32 && ix >= 0 && ix < 32)
                           ? sin[(c * 32 + iy) * 32 + ix] : 0.0f;
            }
            #pragma unroll
            for (int kj = 0; kj < 3; kj++) {
                const float* wp = &sw[((c * 3 + ki) * 3 + kj) * 16];
                #pragma unroll
                for (int o = 0; o < 16; o++) {
                    float wv = wp[o];
                    #pragma unroll
                    for (int xi = 0; xi < 4; xi++)
                        cacc[xi][o] = fmaf(r[xi + kj], wv, cacc[xi][o]);
                }
            }
        }
    }

    // FC: flat index f = o*1024 + y*32 + x0 + xi
    float facc[6];
    #pragma unroll
    for (int j = 0; j < 6; j++) facc[j] = 0.0f;
    const int base = y * 32 + x0;
    #pragma unroll
    for (int j = 0; j < 6; j++) {
        const float* wj = fc_w + (size_t)j * 16384 + base;
        #pragma unroll
        for (int o = 0; o < 16; o++) {
            float4 w4 = *reinterpret_cast<const float4*>(wj + o * 1024);
            facc[j] = fmaf(cacc[0][o], w4.x,
                      fmaf(cacc[1][o], w4.y,
                      fmaf(cacc[2][o], w4.z,
                      fmaf(cacc[3][o], w4.w, facc[j]))));
        }
    }

    #pragma unroll
    for (int j = 0; j < 6; j++) {
        float v = facc[j];
        #pragma unroll
        for (int off = 16; off > 0; off >>= 1)
            v += __shfl_down_sync(0xffffffffu, v, off);
        if ((tid & 31) == 0) sred[(tid >> 5) * 6 + j] = v;
    }
    __syncthreads();
    if (tid < 6) {
        float s = fc_b[tid];
        #pragma unroll
        for (int w = 0; w < 8; w++) s += sred[w * 6 + tid];
        slog[tid] = s;
    }
    __syncthreads();
    if (tid == 0) {
        float mx = slog[0];
        #pragma unroll
        for (int j = 1; j < 6; j++) mx = fmaxf(mx, slog[j]);
        float e[6], s = 0.0f;
        #pragma unroll
        for (int j = 0; j < 6; j++) { e[j] = expf(slog[j] - mx); s += e[j]; }
        float inv = 1.0f / s;
        #pragma unroll
        for (int j = 0; j < 6; j++) out[b * 6 + j] = e[j] * inv;
    }
}

// ===========================================================================
extern "C" void kernel_launch(void* const* d_in, const int* in_sizes, int n_in,
                              void* d_out, int out_size)
{
    const float* x     = (const float*)d_in[0];
    const float* k1    = (const float*)d_in[1];
    const float* gamma = (const float*)d_in[2];
    const float* beta  = (const float*)d_in[3];
    const float* k2    = (const float*)d_in[4];
    const float* k3    = (const float*)d_in[5];
    const float* fc_w  = (const float*)d_in[6];
    const float* fc_b  = (const float*)d_in[7];
    float* out = (float*)d_out;

    k1_conv_bn_pool<<<dim3(4, 8, BATCH), 192>>>(x, k1, gamma, beta);
    k2_conv_pool<<<dim3(2, 4, BATCH), 192>>>(k2);
    k3_conv_fc_softmax<<<BATCH, 256>>>(k3, fc_w, fc_b, out);
}